// round 7
// baseline (speedup 1.0000x reference)
#include <cuda_runtime.h>
#include <cuda_fp16.h>
#include <math.h>
#include <stdint.h>

// ---------------------------------------------------------------------------
// TensorProductMultiLayerPerceptron — Round 6: two-stage GEMM (halved FLOPs)
//
// Stage 1 (GEMM1): Bb[b, p, n] = sum_x hs[b,x] * P_p[x, n]   (n = u*4096+v*64+w)
//                  M=128(b) K=64(x) N=262144 per P  -> 21.5 GF, fp16 out.
// Stage 2 (GEMM2): T[r, w] = sum_uv A[r, uv] * Bb[b(r), p(r), uv*64 + w]
//                  per (b,p): m16(pad) x n64 x K4096 -> memory-bound on Bb.
// A rows (1408): [0,128)=A0(P0) [128,512)=A1(P1) [512,896)=A2(P2)
//                [896,1024)=A3(P3) [1024,1408)=A4(P4)
// ---------------------------------------------------------------------------

#define BATCH 128
#define NROWS 1408

__device__ __half g_Ah[(size_t)NROWS * 4096];
__device__ __half g_hsh[BATCH * 64];
__device__ __half g_Bb[(size_t)BATCH * 5 * 262144];   // 335 MB
__device__ float  g_T[(size_t)NROWS * 64];

// ---------------- helpers ----------------
__device__ __forceinline__ uint32_t smem_u32(const void* p) {
    uint32_t a;
    asm("{ .reg .u64 t; cvta.to.shared.u64 t, %1; cvt.u32.u64 %0, t; }"
        : "=r"(a) : "l"(p));
    return a;
}
__device__ __forceinline__ void cp16(uint32_t s, const void* g) {
    asm volatile("cp.async.cg.shared.global [%0], [%1], 16;\n" :: "r"(s), "l"(g));
}
#define CP_COMMIT() asm volatile("cp.async.commit_group;\n" ::: "memory")
#define CP_WAIT(n)  asm volatile("cp.async.wait_group %0;\n" :: "n"(n) : "memory")

#define LDSM4(r, addr) \
    asm volatile("ldmatrix.sync.aligned.m8n8.x4.shared.b16 {%0,%1,%2,%3}, [%4];" \
        : "=r"((r)[0]), "=r"((r)[1]), "=r"((r)[2]), "=r"((r)[3]) : "r"(addr))
#define LDSM4T(r, addr) \
    asm volatile("ldmatrix.sync.aligned.m8n8.x4.trans.shared.b16 {%0,%1,%2,%3}, [%4];" \
        : "=r"((r)[0]), "=r"((r)[1]), "=r"((r)[2]), "=r"((r)[3]) : "r"(addr))
#define MMA16816(d, a, b0, b1) \
    asm volatile("mma.sync.aligned.m16n8k16.row.col.f32.f16.f16.f32 " \
        "{%0,%1,%2,%3},{%4,%5,%6,%7},{%8,%9},{%0,%1,%2,%3};" \
        : "+f"((d)[0]), "+f"((d)[1]), "+f"((d)[2]), "+f"((d)[3]) \
        : "r"((a)[0]), "r"((a)[1]), "r"((a)[2]), "r"((a)[3]), "r"(b0), "r"(b1))

__device__ __forceinline__ uint32_t pack_h2(float a, float b) {
    __half2 h = __floats2half2_rn(a, b);
    return *reinterpret_cast<uint32_t*>(&h);
}
__device__ __forceinline__ float gelu_tanh(float x) {
    float x3 = x * x * x;
    return 0.5f * x * (1.0f + tanhf(0.7978845608028654f * (x + 0.044715f * x3)));
}

// ---------------------------------------------------------------------------
// Kernel 1: MLP  emb(128x64) -> hs fp16 (g_hsh)
// ---------------------------------------------------------------------------
__global__ __launch_bounds__(256) void mlp_kernel(
    const float* __restrict__ emb, const float* __restrict__ W0,
    const float* __restrict__ W1, const float* __restrict__ W2, float phi_inv)
{
    __shared__ float sa[256];
    __shared__ float sb[256];
    int b = blockIdx.x;
    int t = threadIdx.x;

    if (t < 64) sa[t] = emb[b * 64 + t];
    __syncthreads();

    float acc = 0.0f;
#pragma unroll 8
    for (int k = 0; k < 64; k++) acc += sa[k] * W0[k * 256 + t];
    sb[t] = gelu_tanh(acc * 0.125f) * phi_inv;
    __syncthreads();

    acc = 0.0f;
#pragma unroll 8
    for (int k = 0; k < 256; k++) acc += sb[k] * W1[k * 256 + t];
    float v2l = gelu_tanh(acc * 0.0625f) * phi_inv;
    __syncthreads();
    sa[t] = v2l;
    __syncthreads();

    if (t < 64) {
        acc = 0.0f;
#pragma unroll 8
        for (int k = 0; k < 256; k++) acc += sa[k] * W2[k * 64 + t];
        g_hsh[b * 64 + t] = __float2half(gelu_tanh(acc * 0.0625f) * phi_inv * 0.125f);
    }
}

// ---------------------------------------------------------------------------
// Kernel 2: build A as fp16
// ---------------------------------------------------------------------------
__global__ __launch_bounds__(256) void prepA_kernel(
    const float* __restrict__ x1, const float* __restrict__ x2)
{
    __shared__ float s1[64], s2[64], v1[192], v2[192];
    int b = blockIdx.x;
    int t = threadIdx.x;

    float a1 = x1[b * 256 + t];
    float a2 = x2[b * 256 + t];
    if (t < 64) { s1[t] = a1; s2[t] = a2; }
    else        { v1[t - 64] = a1; v2[t - 64] = a2; }
    __syncthreads();

    __half2* gA2 = (__half2*)g_Ah;
    int rA0 = b;
    int rA1 = 128 + b * 3;
    int rA2 = 512 + b * 3;
    int rA3 = 896 + b;
    int rA4 = 1024 + b * 3;

#pragma unroll
    for (int it = 0; it < 8; it++) {
        int base = it * 512 + t * 2;
        int u = base >> 6;
        int vv = base & 63;
        int col = base >> 1;

        float su = s1[u];
        float sa = s2[vv], sb2 = s2[vv + 1];
        float u0 = v1[u * 3 + 0], u1 = v1[u * 3 + 1], u2 = v1[u * 3 + 2];
        float a0 = v2[vv * 3 + 0], a1v = v2[vv * 3 + 1], a2v = v2[vv * 3 + 2];
        float b0 = v2[vv * 3 + 3], b1v = v2[vv * 3 + 4], b2v = v2[vv * 3 + 5];

        gA2[(size_t)rA0 * 2048 + col] = __floats2half2_rn(su * sa, su * sb2);
        gA2[(size_t)(rA1 + 0) * 2048 + col] = __floats2half2_rn(su * a0,  su * b0);
        gA2[(size_t)(rA1 + 1) * 2048 + col] = __floats2half2_rn(su * a1v, su * b1v);
        gA2[(size_t)(rA1 + 2) * 2048 + col] = __floats2half2_rn(su * a2v, su * b2v);
        gA2[(size_t)(rA2 + 0) * 2048 + col] = __floats2half2_rn(u0 * sa, u0 * sb2);
        gA2[(size_t)(rA2 + 1) * 2048 + col] = __floats2half2_rn(u1 * sa, u1 * sb2);
        gA2[(size_t)(rA2 + 2) * 2048 + col] = __floats2half2_rn(u2 * sa, u2 * sb2);
        gA2[(size_t)rA3 * 2048 + col] = __floats2half2_rn(
            u0 * a0 + u1 * a1v + u2 * a2v, u0 * b0 + u1 * b1v + u2 * b2v);
        gA2[(size_t)(rA4 + 0) * 2048 + col] = __floats2half2_rn(
            u1 * a2v - u2 * a1v, u1 * b2v - u2 * b1v);
        gA2[(size_t)(rA4 + 1) * 2048 + col] = __floats2half2_rn(
            u2 * a0 - u0 * a2v, u2 * b0 - u0 * b2v);
        gA2[(size_t)(rA4 + 2) * 2048 + col] = __floats2half2_rn(
            u0 * a1v - u1 * a0, u0 * b1v - u1 * b0);
    }
}

// ---------------------------------------------------------------------------
// Kernel 3: GEMM1  Bb[b, p, n] = sum_x hsh[b,x] * P_p[x, n]
// grid (512, 5): each CTA does 4 n-chunks of 128.  256 threads (8 warps 4x2).
// Tile per chunk: M=128(b) x N=128 x K=64.  smem: A 16K | Braw 2x32K | Bh 16K.
// ---------------------------------------------------------------------------
#define G1_BRAW 16384
#define G1_BH   81920
#define G1_DSMEM 98304

extern __shared__ char dsm1[];

__global__ void __launch_bounds__(256, 2) gemm1_kernel(
    const float* __restrict__ p0, const float* __restrict__ p1,
    const float* __restrict__ p2, const float* __restrict__ p3,
    const float* __restrict__ p4)
{
    int t = threadIdx.x;
    int lane = t & 31;
    int warp = t >> 5;
    int wm = warp >> 1;              // 0..3
    int wn = warp & 1;               // 0..1
    int p = blockIdx.y;
    int cg = blockIdx.x;             // 0..511

    const float* P = (p == 0) ? p0 : (p == 1) ? p1 : (p == 2) ? p2
                   : (p == 3) ? p3 : p4;
    uint32_t sb = smem_u32(dsm1);

    // ---- stage A (hsh 128x64 fp16) ----
#pragma unroll
    for (int j = 0; j < 4; j++) {
        int idx = t + j * 256;
        int m = idx >> 3, c = idx & 7;
        cp16(sb + m * 128 + ((c ^ (m & 7)) << 4), g_hsh + m * 64 + c * 8);
    }
    // ---- stage Braw chunk 0 into buffer 0 ----
    {
        int chunk = cg * 4;
#pragma unroll
        for (int j = 0; j < 8; j++) {
            int idx = t + j * 256;
            int k = idx >> 5, c = idx & 31;
            cp16(sb + G1_BRAW + k * 512 + c * 16,
                 P + (size_t)k * 262144 + chunk * 128 + c * 4);
        }
    }
    CP_COMMIT();

    int arow_l = lane & 15;
    int hi = lane >> 4;
    int g = lane >> 2, tg = lane & 3;

#pragma unroll 1
    for (int cc = 0; cc < 4; cc++) {
        int chunk = cg * 4 + cc;
        CP_WAIT(0);
        __syncthreads();

        // convert Braw[cc&1] -> Bh fp16 swizzled
        uint32_t braw = sb + G1_BRAW + (cc & 1) * 32768;
#pragma unroll
        for (int j = 0; j < 4; j++) {
            int idx = t + j * 256;
            int k = idx >> 4, c = idx & 15;
            const float4* src = (const float4*)(dsm1 + (braw - sb) + k * 512 + c * 32);
            float4 f0 = src[0], f1 = src[1];
            uint4* dst = (uint4*)(dsm1 + G1_BH + k * 256 + ((c ^ (k & 7)) << 4));
            *dst = make_uint4(pack_h2(f0.x, f0.y), pack_h2(f0.z, f0.w),
                              pack_h2(f1.x, f1.y), pack_h2(f1.z, f1.w));
        }
        __syncthreads();

        // prefetch next chunk's Braw into other buffer
        if (cc < 3) {
            int nchunk = chunk + 1;
            uint32_t dstb = sb + G1_BRAW + ((cc + 1) & 1) * 32768;
#pragma unroll
            for (int j = 0; j < 8; j++) {
                int idx = t + j * 256;
                int k = idx >> 5, c = idx & 31;
                cp16(dstb + k * 512 + c * 16,
                     P + (size_t)k * 262144 + nchunk * 128 + c * 4);
            }
            CP_COMMIT();
        }

        // MMA: K=64 = 4 k16 steps
        float acc[2][8][4];
#pragma unroll
        for (int i = 0; i < 2; i++)
#pragma unroll
            for (int j = 0; j < 8; j++)
#pragma unroll
                for (int k = 0; k < 4; k++) acc[i][j][k] = 0.0f;

#pragma unroll
        for (int kk = 0; kk < 4; kk++) {
            uint32_t a0[4], a1[4];
            {
                int row = wm * 32 + arow_l;
                int c = kk * 2 + hi;
                LDSM4(a0, sb + row * 128 + ((c ^ (row & 7)) << 4));
                row += 16;
                LDSM4(a1, sb + row * 128 + ((c ^ (row & 7)) << 4));
            }
            int krow = kk * 16 + arow_l;
            uint32_t bbase = sb + G1_BH + krow * 256;
            uint32_t kx = (uint32_t)(krow & 7);
#pragma unroll
            for (int nj = 0; nj < 4; nj++) {
                uint32_t c = (uint32_t)(wn * 8 + nj * 2 + hi);
                uint32_t bfr[4];
                LDSM4T(bfr, bbase + ((c ^ kx) << 4));
                MMA16816(acc[0][nj * 2],     a0, bfr[0], bfr[1]);
                MMA16816(acc[0][nj * 2 + 1], a0, bfr[2], bfr[3]);
                MMA16816(acc[1][nj * 2],     a1, bfr[0], bfr[1]);
                MMA16816(acc[1][nj * 2 + 1], a1, bfr[2], bfr[3]);
            }
        }

        // store C (fp16) -> g_Bb
#pragma unroll
        for (int mi = 0; mi < 2; mi++) {
            int bRow = wm * 32 + mi * 16 + g;
            size_t o1 = ((size_t)bRow * 5 + p) * 262144 + (size_t)chunk * 128;
            size_t o2 = ((size_t)(bRow + 8) * 5 + p) * 262144 + (size_t)chunk * 128;
#pragma unroll
            for (int ni = 0; ni < 8; ni++) {
                int n = wn * 64 + ni * 8 + tg * 2;
                __half2 v1 = __floats2half2_rn(acc[mi][ni][0], acc[mi][ni][1]);
                __half2 v2 = __floats2half2_rn(acc[mi][ni][2], acc[mi][ni][3]);
                *(__half2*)&g_Bb[o1 + n] = v1;
                *(__half2*)&g_Bb[o2 + n] = v2;
            }
        }
    }
}

// ---------------------------------------------------------------------------
// Kernel 4: GEMM2  T[r,w] = sum_uv A[r,uv] * Bb[b, p, uv*64 + w]
// grid (128 b, 5 p) = 640 CTAs, 128 threads (4 warps, warp = n16).
// m16 (rows padded, clamped to row 0), K=4096 in 64 blocks, 4-stage pipeline.
// Stage: A[16][64]h (2KB) + B[64][64]h (8KB) = 10240 B; 4 stages = 40960 B.
// ---------------------------------------------------------------------------
__global__ void __launch_bounds__(128) gemm2_kernel()
{
    __shared__ char sm2[4 * 10240];
    int t = threadIdx.x;
    int lane = t & 31;
    int warp = t >> 5;
    int b = blockIdx.x;
    int p = blockIdx.y;

    int cnt   = (p == 1 || p == 2 || p == 4) ? 3 : 1;
    int rbase = (p == 0) ? b : (p == 1) ? 128 + 3 * b : (p == 2) ? 512 + 3 * b
              : (p == 3) ? 896 + b : 1024 + 3 * b;

    uint32_t sb = smem_u32(sm2);
    size_t bp = ((size_t)b * 5 + p) * 262144;

    // loader coords
    int arow = t >> 3, ac = t & 7;
    int asrcRow = rbase + (arow < cnt ? arow : 0);
    const __half* asrc = g_Ah + (size_t)asrcRow * 4096 + ac * 8;
    uint32_t adst = (uint32_t)(arow * 128 + ((ac ^ (arow & 7)) << 4));

    // prologue: stages 0..2
#pragma unroll
    for (int s = 0; s < 3; s++) {
        int k0 = s * 64;
        uint32_t st = sb + s * 10240;
        cp16(st + adst, asrc + k0);
#pragma unroll
        for (int j = 0; j < 4; j++) {
            int idx = t + j * 128;
            int kr = idx >> 3, c = idx & 7;
            cp16(st + 2048 + kr * 128 + ((c ^ (kr & 7)) << 4),
                 g_Bb + bp + (size_t)(k0 + kr) * 64 + c * 8);
        }
        CP_COMMIT();
    }

    float acc[2][4];
#pragma unroll
    for (int i = 0; i < 2; i++)
#pragma unroll
        for (int j = 0; j < 4; j++) acc[i][j] = 0.0f;

    int arl = lane & 15;
    int hi = lane >> 4;

#pragma unroll 1
    for (int i = 0; i < 64; i++) {
        CP_WAIT(2);
        __syncthreads();

        if (i + 3 < 64) {
            int k0 = (i + 3) * 64;
            uint32_t st = sb + ((i + 3) & 3) * 10240;
            cp16(st + adst, asrc + k0);
#pragma unroll
            for (int j = 0; j < 4; j++) {
                int idx = t + j * 128;
                int kr = idx >> 3, c = idx & 7;
                cp16(st + 2048 + kr * 128 + ((c ^ (kr & 7)) << 4),
                     g_Bb + bp + (size_t)(k0 + kr) * 64 + c * 8);
            }
        }
        CP_COMMIT();

        uint32_t st = sb + (i & 3) * 10240;
#pragma unroll
        for (int kk = 0; kk < 4; kk++) {
            uint32_t a[4];
            {
                int c = kk * 2 + hi;
                LDSM4(a, st + arl * 128 + ((c ^ (arl & 7)) << 4));
            }
            int krow = kk * 16 + arl;
            uint32_t c = (uint32_t)(warp * 2 + hi);
            uint32_t bf[4];
            LDSM4T(bf, st + 2048 + krow * 128 + ((c ^ (uint32_t)(krow & 7)) << 4));
            MMA16816(acc[0], a, bf[0], bf[1]);
            MMA16816(acc[1], a, bf[2], bf[3]);
        }
    }

    // epilogue: rows g < cnt are real (cnt <= 3 so row g+8 never valid)
    int g = lane >> 2, tg = lane & 3;
    if (g < cnt) {
        int w = warp * 16 + tg * 2;
        *(float2*)&g_T[(size_t)(rbase + g) * 64 + w]     = make_float2(acc[0][0], acc[0][1]);
        *(float2*)&g_T[(size_t)(rbase + g) * 64 + w + 8] = make_float2(acc[1][0], acc[1][1]);
    }
}

// ---------------------------------------------------------------------------
// Kernel 5: combine to output
// ---------------------------------------------------------------------------
__global__ __launch_bounds__(448) void combine_kernel(float* __restrict__ out)
{
    int b = blockIdx.x;
    int t = threadIdx.x;
    const float C = 0.011048543456039806f;       // 1/(64*sqrt(2))
    const float INV_SQ3 = 0.5773502691896258f;

    if (t < 64) {
        int w = t;
        out[b * 448 + w] = C * (g_T[(size_t)b * 64 + w]
                              + INV_SQ3 * g_T[(size_t)(896 + b) * 64 + w]);
    } else if (t < 256) {
        int i = t - 64;
        int w = i / 3, c = i % 3;
        out[b * 448 + 64 + w * 3 + c] =
            C * (g_T[(size_t)(128 + b * 3 + c) * 64 + w]
               + g_T[(size_t)(512 + b * 3 + c) * 64 + w]);
    } else {
        int i = t - 256;
        int w = i / 3, k = i % 3;
        out[b * 448 + 256 + w * 3 + k] =
            C * g_T[(size_t)(1024 + b * 3 + k) * 64 + w];
    }
}

// ---------------------------------------------------------------------------
static double host_phi_c()
{
    const double dz = 16.0 / 4000.0;
    const double inv_sqrt2pi = 0.3989422804014327;
    double sum = 0.0, prev = 0.0;
    for (int i = 0; i <= 4000; i++) {
        double z = -8.0 + dz * (double)i;
        float xf = (float)z;
        float x3 = xf * xf * xf;
        float gg = 0.5f * xf * (1.0f + tanhf(0.7978845608028654f * (xf + 0.044715f * x3)));
        double f = (double)gg * (double)gg * exp(-0.5 * z * z) * inv_sqrt2pi;
        if (i > 0) sum += 0.5 * (f + prev) * dz;
        prev = f;
    }
    return sqrt(sum);
}

extern "C" void kernel_launch(void* const* d_in, const int* in_sizes, int n_in,
                              void* d_out, int out_size)
{
    const float* emb = (const float*)d_in[0];
    const float* x1  = (const float*)d_in[1];
    const float* x2  = (const float*)d_in[2];
    const float* W0  = (const float*)d_in[3];
    const float* W1  = (const float*)d_in[4];
    const float* W2  = (const float*)d_in[5];
    const float* P0  = (const float*)d_in[6];
    const float* P1  = (const float*)d_in[7];
    const float* P2  = (const float*)d_in[8];
    const float* P3  = (const float*)d_in[9];
    const float* P4  = (const float*)d_in[10];
    float* out = (float*)d_out;

    float phi_inv = (float)(1.0 / host_phi_c());

    cudaFuncSetAttribute(gemm1_kernel,
                         cudaFuncAttributeMaxDynamicSharedMemorySize, G1_DSMEM);

    mlp_kernel<<<128, 256>>>(emb, W0, W1, W2, phi_inv);
    prepA_kernel<<<128, 256>>>(x1, x2);
    gemm1_kernel<<<dim3(512, 5), 256, G1_DSMEM>>>(P0, P1, P2, P3, P4);
    gemm2_kernel<<<dim3(128, 5), 128>>>();
    combine_kernel<<<128, 448>>>(out);
}

// round 8
// speedup vs baseline: 1.6361x; 1.6361x over previous
#include <cuda_runtime.h>
#include <cuda_fp16.h>
#include <math.h>
#include <stdint.h>

// ---------------------------------------------------------------------------
// TensorProductMultiLayerPerceptron — Round 7: fully fused single pass over P
//
// For each (p, u, wh) CTA, loop v:
//   Bb[b, w] = sum_x hs[b,x] * P_p[x, u, v, w]          (fp16 mma, fp32 acc)
//   T_acc[set][b, w] += weight_p(b, v) * Bb[b, w]       (registers)
// Epilogue: apply u-factor, write per-u partials; combine reduces over u.
// ---------------------------------------------------------------------------

#define NROWS 1408

__device__ __half g_hsh[128 * 64];
__device__ float  g_s2t[64 * 128];        // [v][b] = s2[b,v]
__device__ float  g_v2t[3][64 * 128];     // [j][v][b] = v2[b,v,j]
__device__ float  g_part[(size_t)64 * NROWS * 64];   // [u][r][w], 23 MB

// ---------------- helpers ----------------
__device__ __forceinline__ uint32_t smem_u32(const void* p) {
    uint32_t a;
    asm("{ .reg .u64 t; cvta.to.shared.u64 t, %1; cvt.u32.u64 %0, t; }"
        : "=r"(a) : "l"(p));
    return a;
}
__device__ __forceinline__ void cp16(uint32_t s, const void* g) {
    asm volatile("cp.async.cg.shared.global [%0], [%1], 16;\n" :: "r"(s), "l"(g));
}
#define CP_COMMIT() asm volatile("cp.async.commit_group;\n" ::: "memory")
#define CP_WAIT(n)  asm volatile("cp.async.wait_group %0;\n" :: "n"(n) : "memory")

#define LDSM4(r, addr) \
    asm volatile("ldmatrix.sync.aligned.m8n8.x4.shared.b16 {%0,%1,%2,%3}, [%4];" \
        : "=r"((r)[0]), "=r"((r)[1]), "=r"((r)[2]), "=r"((r)[3]) : "r"(addr))
#define LDSM4T(r, addr) \
    asm volatile("ldmatrix.sync.aligned.m8n8.x4.trans.shared.b16 {%0,%1,%2,%3}, [%4];" \
        : "=r"((r)[0]), "=r"((r)[1]), "=r"((r)[2]), "=r"((r)[3]) : "r"(addr))
#define MMA16816(d, a, b0, b1) \
    asm volatile("mma.sync.aligned.m16n8k16.row.col.f32.f16.f16.f32 " \
        "{%0,%1,%2,%3},{%4,%5,%6,%7},{%8,%9},{%0,%1,%2,%3};" \
        : "+f"((d)[0]), "+f"((d)[1]), "+f"((d)[2]), "+f"((d)[3]) \
        : "r"((a)[0]), "r"((a)[1]), "r"((a)[2]), "r"((a)[3]), "r"(b0), "r"(b1))

__device__ __forceinline__ uint32_t pack_h2(float a, float b) {
    __half2 h = __floats2half2_rn(a, b);
    return *reinterpret_cast<uint32_t*>(&h);
}
__device__ __forceinline__ float gelu_tanh(float x) {
    float x3 = x * x * x;
    return 0.5f * x * (1.0f + tanhf(0.7978845608028654f * (x + 0.044715f * x3)));
}

// ---------------------------------------------------------------------------
// Kernel 1: MLP  emb(128x64) -> hs fp16
// ---------------------------------------------------------------------------
__global__ __launch_bounds__(256) void mlp_kernel(
    const float* __restrict__ emb, const float* __restrict__ W0,
    const float* __restrict__ W1, const float* __restrict__ W2, float phi_inv)
{
    __shared__ float sa[256];
    __shared__ float sb[256];
    int b = blockIdx.x;
    int t = threadIdx.x;

    if (t < 64) sa[t] = emb[b * 64 + t];
    __syncthreads();

    float acc = 0.0f;
#pragma unroll 8
    for (int k = 0; k < 64; k++) acc += sa[k] * W0[k * 256 + t];
    sb[t] = gelu_tanh(acc * 0.125f) * phi_inv;
    __syncthreads();

    acc = 0.0f;
#pragma unroll 8
    for (int k = 0; k < 256; k++) acc += sb[k] * W1[k * 256 + t];
    float v2l = gelu_tanh(acc * 0.0625f) * phi_inv;
    __syncthreads();
    sa[t] = v2l;
    __syncthreads();

    if (t < 64) {
        acc = 0.0f;
#pragma unroll 8
        for (int k = 0; k < 256; k++) acc += sa[k] * W2[k * 64 + t];
        g_hsh[b * 64 + t] = __float2half(gelu_tanh(acc * 0.0625f) * phi_inv * 0.125f);
    }
}

// ---------------------------------------------------------------------------
// Kernel 2: weight tables  s2t[v][b], v2t[j][v][b]
// ---------------------------------------------------------------------------
__global__ __launch_bounds__(128) void prepW_kernel(const float* __restrict__ x2)
{
    int v = blockIdx.x;      // 0..63
    int b = threadIdx.x;     // 0..127
    g_s2t[v * 128 + b] = x2[b * 256 + v];
#pragma unroll
    for (int j = 0; j < 3; j++)
        g_v2t[j][v * 128 + b] = x2[b * 256 + 64 + v * 3 + j];
}

// ---------------------------------------------------------------------------
// Kernel 3: fused GEMM.  grid (64 u, 2 wh, 5 p) = 640 CTAs, 256 threads
// (8 warps, warp = m16 x n32).  smem: hs 16K | praw 3x8K | bh 2x4K = 48K.
// ---------------------------------------------------------------------------
#define SM_HS 0
#define SM_PR 16384
#define SM_BH 40960

__global__ void __launch_bounds__(256, 2) fused_kernel(
    const float* __restrict__ p0, const float* __restrict__ p1,
    const float* __restrict__ p2, const float* __restrict__ p3,
    const float* __restrict__ p4, const float* __restrict__ x1)
{
    __shared__ __align__(16) char sm[49152];
    uint32_t sb = smem_u32(sm);

    int t = threadIdx.x;
    int lane = t & 31;
    int warp = t >> 5;           // 0..7 -> m16 tile
    int u  = blockIdx.x;         // 0..63
    int wh = blockIdx.y;         // 0..1
    int p  = blockIdx.z;         // 0..4

    const float* P = (p == 0) ? p0 : (p == 1) ? p1 : (p == 2) ? p2
                   : (p == 3) ? p3 : p4;

    // ---- stage hs (128 x 64 fp16, swizzled): group Ghs ----
#pragma unroll
    for (int j = 0; j < 4; j++) {
        int idx = t + j * 256;
        int m = idx >> 3, c = idx & 7;
        cp16(sb + SM_HS + m * 128 + ((c ^ (m & 7)) << 4), g_hsh + m * 64 + c * 8);
    }
    CP_COMMIT();

    // per-thread P loader coords (2 chunks of 16B per thread per v)
    const float* psrc[2];
    uint32_t pdst[2];
#pragma unroll
    for (int j = 0; j < 2; j++) {
        int idx = t + j * 256;
        int x = idx >> 3, c = idx & 7;
        psrc[j] = P + (size_t)(x * 64 + u) * 4096 + wh * 32 + c * 4;
        pdst[j] = (uint32_t)(SM_PR + x * 128 + c * 16);
    }

    // ---- prologue: P slices v=0 (buf0), v=1 (buf1) ----
#pragma unroll
    for (int s = 0; s < 2; s++) {
#pragma unroll
        for (int j = 0; j < 2; j++)
            cp16(sb + pdst[j] + s * 8192, psrc[j] + s * 64);
        CP_COMMIT();
    }

    // ---- wait for hs, load persistent A fragments ----
    CP_WAIT(2);
    __syncthreads();
    uint32_t af[4][4];
    {
        int row = warp * 16 + (lane & 15);
        int hi = lane >> 4;
#pragma unroll
        for (int kk = 0; kk < 4; kk++) {
            int c = kk * 2 + hi;
            LDSM4(af[kk], sb + SM_HS + row * 128 + ((c ^ (row & 7)) << 4));
        }
    }

    // persistent per-thread row data
    int b1 = warp * 16 + (lane >> 2);
    int b2 = b1 + 8;
    float v1a[3], v1b[3];
#pragma unroll
    for (int i = 0; i < 3; i++) {
        v1a[i] = x1[b1 * 256 + 64 + u * 3 + i];
        v1b[i] = x1[b2 * 256 + 64 + u * 3 + i];
    }

    float Tacc[48];
#pragma unroll
    for (int i = 0; i < 48; i++) Tacc[i] = 0.0f;

    int hi = lane >> 4;
    int krl = lane & 15;

    // ================= main v loop =================
#pragma unroll 1
    for (int v = 0; v < 64; v++) {
        CP_WAIT(1);
        __syncthreads();

        // convert praw[v%3] (fp32 64x32) -> bh[v&1] (fp16 swizzled)
        {
            int k = t >> 2, c = t & 3;
            const float4* src = (const float4*)(sm + SM_PR + (v % 3) * 8192
                                                + k * 128 + c * 32);
            float4 f0 = src[0], f1 = src[1];
            uint4* dst = (uint4*)(sm + SM_BH + (v & 1) * 4096
                                  + k * 64 + ((c ^ ((k >> 1) & 3)) << 4));
            *dst = make_uint4(pack_h2(f0.x, f0.y), pack_h2(f0.z, f0.w),
                              pack_h2(f1.x, f1.y), pack_h2(f1.z, f1.w));
        }
        __syncthreads();

        // issue P slice v+2 into praw[(v+2)%3]
        if (v + 2 < 64) {
#pragma unroll
            for (int j = 0; j < 2; j++)
                cp16(sb + pdst[j] + ((v + 2) % 3) * 8192, psrc[j] + (v + 2) * 64);
        }
        CP_COMMIT();

        // ---- mma: Bb_slice[128 b, 32 w] ----
        float acc[4][4];
#pragma unroll
        for (int nj = 0; nj < 4; nj++)
#pragma unroll
            for (int q = 0; q < 4; q++) acc[nj][q] = 0.0f;

        uint32_t bhbase = sb + SM_BH + (v & 1) * 4096;
#pragma unroll
        for (int kk = 0; kk < 4; kk++) {
            int krow = kk * 16 + krl;
            uint32_t rowb = bhbase + krow * 64;
            uint32_t sw = (uint32_t)((krow >> 1) & 3);
            uint32_t bf0[4], bf1[4];
            LDSM4T(bf0, rowb + (((uint32_t)hi ^ sw) << 4));
            LDSM4T(bf1, rowb + (((uint32_t)(2 + hi) ^ sw) << 4));
            MMA16816(acc[0], af[kk], bf0[0], bf0[1]);
            MMA16816(acc[1], af[kk], bf0[2], bf0[3]);
            MMA16816(acc[2], af[kk], bf1[0], bf1[1]);
            MMA16816(acc[3], af[kk], bf1[2], bf1[3]);
        }

        // ---- weighted accumulate ----
        int vb = v * 128;
        if (p == 0 || p == 2) {
            float w1 = g_s2t[vb + b1], w2 = g_s2t[vb + b2];
#pragma unroll
            for (int nj = 0; nj < 4; nj++) {
                Tacc[nj * 4 + 0] += w1 * acc[nj][0];
                Tacc[nj * 4 + 1] += w1 * acc[nj][1];
                Tacc[nj * 4 + 2] += w2 * acc[nj][2];
                Tacc[nj * 4 + 3] += w2 * acc[nj][3];
            }
        } else if (p == 3) {
            float w1 = v1a[0] * g_v2t[0][vb + b1] + v1a[1] * g_v2t[1][vb + b1]
                     + v1a[2] * g_v2t[2][vb + b1];
            float w2 = v1b[0] * g_v2t[0][vb + b2] + v1b[1] * g_v2t[1][vb + b2]
                     + v1b[2] * g_v2t[2][vb + b2];
#pragma unroll
            for (int nj = 0; nj < 4; nj++) {
                Tacc[nj * 4 + 0] += w1 * acc[nj][0];
                Tacc[nj * 4 + 1] += w1 * acc[nj][1];
                Tacc[nj * 4 + 2] += w2 * acc[nj][2];
                Tacc[nj * 4 + 3] += w2 * acc[nj][3];
            }
        } else {
            float wa[3], wb[3];
            if (p == 1) {
#pragma unroll
                for (int j = 0; j < 3; j++) {
                    wa[j] = g_v2t[j][vb + b1];
                    wb[j] = g_v2t[j][vb + b2];
                }
            } else {  // p == 4: cross(v1, v2)
                float y0 = g_v2t[0][vb + b1], y1 = g_v2t[1][vb + b1], y2 = g_v2t[2][vb + b1];
                wa[0] = v1a[1] * y2 - v1a[2] * y1;
                wa[1] = v1a[2] * y0 - v1a[0] * y2;
                wa[2] = v1a[0] * y1 - v1a[1] * y0;
                float z0 = g_v2t[0][vb + b2], z1 = g_v2t[1][vb + b2], z2 = g_v2t[2][vb + b2];
                wb[0] = v1b[1] * z2 - v1b[2] * z1;
                wb[1] = v1b[2] * z0 - v1b[0] * z2;
                wb[2] = v1b[0] * z1 - v1b[1] * z0;
            }
#pragma unroll
            for (int s = 0; s < 3; s++)
#pragma unroll
                for (int nj = 0; nj < 4; nj++) {
                    Tacc[s * 16 + nj * 4 + 0] += wa[s] * acc[nj][0];
                    Tacc[s * 16 + nj * 4 + 1] += wa[s] * acc[nj][1];
                    Tacc[s * 16 + nj * 4 + 2] += wb[s] * acc[nj][2];
                    Tacc[s * 16 + nj * 4 + 3] += wb[s] * acc[nj][3];
                }
        }
    }

    // ---- epilogue: apply u-factor, write per-u partials ----
    size_t pb = (size_t)u * (NROWS * 64);
    int wb0 = wh * 32 + (lane & 3) * 2;

    auto store_rows = [&](int row1, int row2, int set, float f1, float f2) {
#pragma unroll
        for (int nj = 0; nj < 4; nj++) {
            int w = wb0 + nj * 8;
            *(float2*)&g_part[pb + (size_t)row1 * 64 + w] =
                make_float2(f1 * Tacc[set * 16 + nj * 4 + 0],
                            f1 * Tacc[set * 16 + nj * 4 + 1]);
            *(float2*)&g_part[pb + (size_t)row2 * 64 + w] =
                make_float2(f2 * Tacc[set * 16 + nj * 4 + 2],
                            f2 * Tacc[set * 16 + nj * 4 + 3]);
        }
    };

    if (p == 0) {
        float s1a = x1[b1 * 256 + u], s1b = x1[b2 * 256 + u];
        store_rows(b1, b2, 0, s1a, s1b);
    } else if (p == 1) {
        float s1a = x1[b1 * 256 + u], s1b = x1[b2 * 256 + u];
#pragma unroll
        for (int j = 0; j < 3; j++)
            store_rows(128 + 3 * b1 + j, 128 + 3 * b2 + j, j, s1a, s1b);
    } else if (p == 2) {
#pragma unroll
        for (int i = 0; i < 3; i++)
            store_rows(512 + 3 * b1 + i, 512 + 3 * b2 + i, 0, v1a[i], v1b[i]);
    } else if (p == 3) {
        store_rows(896 + b1, 896 + b2, 0, 1.0f, 1.0f);
    } else {
#pragma unroll
        for (int k = 0; k < 3; k++)
            store_rows(1024 + 3 * b1 + k, 1024 + 3 * b2 + k, k, 1.0f, 1.0f);
    }
}

// ---------------------------------------------------------------------------
// Kernel 4: combine — reduce over u and assemble output
// ---------------------------------------------------------------------------
__global__ __launch_bounds__(448) void combine_kernel(float* __restrict__ out)
{
    int b = blockIdx.x;
    int t = threadIdx.x;
    const float C = 0.011048543456039806f;       // 1/(64*sqrt(2))
    const float INV_SQ3 = 0.5773502691896258f;
    const size_t US = (size_t)NROWS * 64;

    if (t < 64) {
        int w = t;
        float s = 0.0f;
#pragma unroll 4
        for (int u = 0; u < 64; u++)
            s += g_part[u * US + (size_t)b * 64 + w]
               + INV_SQ3 * g_part[u * US + (size_t)(896 + b) * 64 + w];
        out[b * 448 + w] = C * s;
    } else if (t < 256) {
        int i = t - 64;
        int w = i / 3, c = i % 3;
        float s = 0.0f;
#pragma unroll 4
        for (int u = 0; u < 64; u++)
            s += g_part[u * US + (size_t)(128 + b * 3 + c) * 64 + w]
               + g_part[u * US + (size_t)(512 + b * 3 + c) * 64 + w];
        out[b * 448 + 64 + w * 3 + c] = C * s;
    } else {
        int i = t - 256;
        int w = i / 3, k = i % 3;
        float s = 0.0f;
#pragma unroll 4
        for (int u = 0; u < 64; u++)
            s += g_part[u * US + (size_t)(1024 + b * 3 + k) * 64 + w];
        out[b * 448 + 256 + w * 3 + k] = C * s;
    }
}

// ---------------------------------------------------------------------------
static double host_phi_c()
{
    const double dz = 16.0 / 4000.0;
    const double inv_sqrt2pi = 0.3989422804014327;
    double sum = 0.0, prev = 0.0;
    for (int i = 0; i <= 4000; i++) {
        double z = -8.0 + dz * (double)i;
        float xf = (float)z;
        float x3 = xf * xf * xf;
        float gg = 0.5f * xf * (1.0f + tanhf(0.7978845608028654f * (xf + 0.044715f * x3)));
        double f = (double)gg * (double)gg * exp(-0.5 * z * z) * inv_sqrt2pi;
        if (i > 0) sum += 0.5 * (f + prev) * dz;
        prev = f;
    }
    return sqrt(sum);
}

extern "C" void kernel_launch(void* const* d_in, const int* in_sizes, int n_in,
                              void* d_out, int out_size)
{
    const float* emb = (const float*)d_in[0];
    const float* x1  = (const float*)d_in[1];
    const float* x2  = (const float*)d_in[2];
    const float* W0  = (const float*)d_in[3];
    const float* W1  = (const float*)d_in[4];
    const float* W2  = (const float*)d_in[5];
    const float* P0  = (const float*)d_in[6];
    const float* P1  = (const float*)d_in[7];
    const float* P2  = (const float*)d_in[8];
    const float* P3  = (const float*)d_in[9];
    const float* P4  = (const float*)d_in[10];
    float* out = (float*)d_out;

    float phi_inv = (float)(1.0 / host_phi_c());

    mlp_kernel<<<128, 256>>>(emb, W0, W1, W2, phi_inv);
    prepW_kernel<<<64, 128>>>(x2);
    fused_kernel<<<dim3(64, 2, 5), 256>>>(P0, P1, P2, P3, P4, x1);
    combine_kernel<<<128, 448>>>(out);
}

// round 9
// speedup vs baseline: 2.0313x; 1.2416x over previous
#include <cuda_runtime.h>
#include <cuda_fp16.h>
#include <math.h>
#include <stdint.h>

// ---------------------------------------------------------------------------
// TensorProductMultiLayerPerceptron — Round 8: fused, 4-v batches, atomic T
//
// For each (p, u, wh, kz) CTA, loop v in its 32-v half (8 iterations x 4 v):
//   Bb[b, w] = sum_x hs[b,x] * P_p[x, u, v, w]        (fp16 mma, fp32 acc)
//   T_acc[set][b, w] += weight_p(b, v) * Bb[b, w]     (registers)
// Epilogue: apply u-factor, atomicAdd into g_T[1408 x 64]; combine assembles.
// ---------------------------------------------------------------------------

#define NROWS 1408

__device__ __half g_hsh[128 * 64];
__device__ float  g_s2t[64 * 128];        // [v][b] = s2[b,v]
__device__ float  g_v2t[3][64 * 128];     // [j][v][b] = v2[b,v,j]
__device__ float  g_T[NROWS * 64];

// ---------------- helpers ----------------
__device__ __forceinline__ uint32_t smem_u32(const void* p) {
    uint32_t a;
    asm("{ .reg .u64 t; cvta.to.shared.u64 t, %1; cvt.u32.u64 %0, t; }"
        : "=r"(a) : "l"(p));
    return a;
}
__device__ __forceinline__ void cp16(uint32_t s, const void* g) {
    asm volatile("cp.async.cg.shared.global [%0], [%1], 16;\n" :: "r"(s), "l"(g));
}
#define CP_COMMIT() asm volatile("cp.async.commit_group;\n" ::: "memory")
#define CP_WAIT(n)  asm volatile("cp.async.wait_group %0;\n" :: "n"(n) : "memory")

#define LDSM4(r, addr) \
    asm volatile("ldmatrix.sync.aligned.m8n8.x4.shared.b16 {%0,%1,%2,%3}, [%4];" \
        : "=r"((r)[0]), "=r"((r)[1]), "=r"((r)[2]), "=r"((r)[3]) : "r"(addr))
#define LDSM4T(r, addr) \
    asm volatile("ldmatrix.sync.aligned.m8n8.x4.trans.shared.b16 {%0,%1,%2,%3}, [%4];" \
        : "=r"((r)[0]), "=r"((r)[1]), "=r"((r)[2]), "=r"((r)[3]) : "r"(addr))
#define MMA16816(d, a, b0, b1) \
    asm volatile("mma.sync.aligned.m16n8k16.row.col.f32.f16.f16.f32 " \
        "{%0,%1,%2,%3},{%4,%5,%6,%7},{%8,%9},{%0,%1,%2,%3};" \
        : "+f"((d)[0]), "+f"((d)[1]), "+f"((d)[2]), "+f"((d)[3]) \
        : "r"((a)[0]), "r"((a)[1]), "r"((a)[2]), "r"((a)[3]), "r"(b0), "r"(b1))

__device__ __forceinline__ uint32_t pack_h2(float a, float b) {
    __half2 h = __floats2half2_rn(a, b);
    return *reinterpret_cast<uint32_t*>(&h);
}
__device__ __forceinline__ float gelu_tanh(float x) {
    float x3 = x * x * x;
    return 0.5f * x * (1.0f + tanhf(0.7978845608028654f * (x + 0.044715f * x3)));
}

// ---------------------------------------------------------------------------
// Kernel 1: MLP  emb(128x64) -> hs fp16
// ---------------------------------------------------------------------------
__global__ __launch_bounds__(256) void mlp_kernel(
    const float* __restrict__ emb, const float* __restrict__ W0,
    const float* __restrict__ W1, const float* __restrict__ W2, float phi_inv)
{
    __shared__ float sa[256];
    __shared__ float sb[256];
    int b = blockIdx.x;
    int t = threadIdx.x;

    if (t < 64) sa[t] = emb[b * 64 + t];
    __syncthreads();

    float acc = 0.0f;
#pragma unroll 8
    for (int k = 0; k < 64; k++) acc += sa[k] * W0[k * 256 + t];
    sb[t] = gelu_tanh(acc * 0.125f) * phi_inv;
    __syncthreads();

    acc = 0.0f;
#pragma unroll 8
    for (int k = 0; k < 256; k++) acc += sb[k] * W1[k * 256 + t];
    float v2l = gelu_tanh(acc * 0.0625f) * phi_inv;
    __syncthreads();
    sa[t] = v2l;
    __syncthreads();

    if (t < 64) {
        acc = 0.0f;
#pragma unroll 8
        for (int k = 0; k < 256; k++) acc += sa[k] * W2[k * 64 + t];
        g_hsh[b * 64 + t] = __float2half(gelu_tanh(acc * 0.0625f) * phi_inv * 0.125f);
    }
}

// ---------------------------------------------------------------------------
// Kernel 2: weight tables + zero g_T
// ---------------------------------------------------------------------------
__global__ __launch_bounds__(128) void prepW_kernel(const float* __restrict__ x2)
{
    int v = blockIdx.x;      // 0..63
    int b = threadIdx.x;     // 0..127
    g_s2t[v * 128 + b] = x2[b * 256 + v];
#pragma unroll
    for (int j = 0; j < 3; j++)
        g_v2t[j][v * 128 + b] = x2[b * 256 + 64 + v * 3 + j];
}
__global__ void zeroT_kernel()
{
    g_T[blockIdx.x * 1024 + threadIdx.x] = 0.0f;
}

// ---------------------------------------------------------------------------
// Kernel 3: fused GEMM.  grid (64 u, 2 wh, 10 = p*2+kz), 256 threads.
// smem: hs 16K | praw 2 x 32K (4-v quads, fp32) | bh 16K (4 x 4K fp16).
// ---------------------------------------------------------------------------
#define SM_HS 0
#define SM_PR 16384
#define SM_BH 81920
#define FUSED_DSMEM 98304

extern __shared__ char dsm[];

__global__ void __launch_bounds__(256, 2) fused_kernel(
    const float* __restrict__ p0, const float* __restrict__ p1,
    const float* __restrict__ p2, const float* __restrict__ p3,
    const float* __restrict__ p4, const float* __restrict__ x1)
{
    uint32_t sb = smem_u32(dsm);

    int t = threadIdx.x;
    int lane = t & 31;
    int warp = t >> 5;           // 0..7 -> m16 tile
    int u  = blockIdx.x;         // 0..63
    int wh = blockIdx.y;         // 0..1
    int p  = blockIdx.z >> 1;    // 0..4
    int kz = blockIdx.z & 1;     // 0..1
    int v0 = kz * 32;

    const float* P = (p == 0) ? p0 : (p == 1) ? p1 : (p == 2) ? p2
                   : (p == 3) ? p3 : p4;

    // ---- stage hs (128 x 64 fp16, swizzled) ----
#pragma unroll
    for (int j = 0; j < 4; j++) {
        int idx = t + j * 256;
        int m = idx >> 3, c = idx & 7;
        cp16(sb + SM_HS + m * 128 + ((c ^ (m & 7)) << 4), g_hsh + m * 64 + c * 8);
    }

    // P loader: per thread 8 chunks per 4-v quad.
    // chunk j: x = (t>>3) + (j&1)*32, vv = j>>1, c = t&7
    const float* pbase = P + (size_t)((t >> 3) * 64 + u) * 4096
                       + (size_t)v0 * 64 + wh * 32 + (t & 7) * 4;
    uint32_t pdst = (uint32_t)(SM_PR + (t >> 3) * 128 + (t & 7) * 16);
    const size_t XSTEP = (size_t)32 * 64 * 4096;   // x += 32

    // ---- prologue: quad 0 into buf 0 ----
#pragma unroll
    for (int j = 0; j < 8; j++)
        cp16(sb + pdst + (j & 1) * 4096 + (j >> 1) * 8192,
             pbase + (j & 1) * XSTEP + (size_t)(j >> 1) * 64);
    CP_COMMIT();
    CP_WAIT(0);
    __syncthreads();

    // persistent hs A-fragments
    uint32_t af[4][4];
    {
        int row = warp * 16 + (lane & 15);
        int hi = lane >> 4;
#pragma unroll
        for (int kk = 0; kk < 4; kk++) {
            int c = kk * 2 + hi;
            LDSM4(af[kk], sb + SM_HS + row * 128 + ((c ^ (row & 7)) << 4));
        }
    }

    // persistent per-thread row data
    int b1 = warp * 16 + (lane >> 2);
    int b2 = b1 + 8;
    float v1a[3], v1b[3];
#pragma unroll
    for (int i = 0; i < 3; i++) {
        v1a[i] = x1[b1 * 256 + 64 + u * 3 + i];
        v1b[i] = x1[b2 * 256 + 64 + u * 3 + i];
    }

    float Tacc[48];
#pragma unroll
    for (int i = 0; i < 48; i++) Tacc[i] = 0.0f;

    int hi = lane >> 4;
    int krl = lane & 15;

    // ================= main loop: 8 iterations x 4 v =================
#pragma unroll 1
    for (int i = 0; i < 8; i++) {
        int buf = i & 1;
        CP_WAIT(0);
        __syncthreads();

        // prefetch quad i+1 into buf^1 (issued early, covered by full iteration)
        if (i + 1 < 8) {
            const float* src = pbase + (size_t)(i + 1) * 256;
            uint32_t dst = sb + pdst + (buf ^ 1) * 32768;
#pragma unroll
            for (int j = 0; j < 8; j++)
                cp16(dst + (j & 1) * 4096 + (j >> 1) * 8192,
                     src + (j & 1) * XSTEP + (size_t)(j >> 1) * 64);
        }
        CP_COMMIT();

        // convert praw[buf] (4 x 8KB fp32) -> bh (4 x 4KB fp16, swizzled)
        {
            int k = t >> 2, c = t & 3;
            const char* srcb = dsm + SM_PR + buf * 32768 + k * 128 + c * 32;
            char* dstb = dsm + SM_BH + k * 64 + ((c ^ ((k >> 1) & 3)) << 4);
#pragma unroll
            for (int vv = 0; vv < 4; vv++) {
                const float4* src = (const float4*)(srcb + vv * 8192);
                float4 f0 = src[0], f1 = src[1];
                *(uint4*)(dstb + vv * 4096) =
                    make_uint4(pack_h2(f0.x, f0.y), pack_h2(f0.z, f0.w),
                               pack_h2(f1.x, f1.y), pack_h2(f1.z, f1.w));
            }
        }
        __syncthreads();

        // ---- 4 v: mma + weighted accumulate ----
#pragma unroll
        for (int vv = 0; vv < 4; vv++) {
            int v = v0 + i * 4 + vv;
            float acc[4][4];
#pragma unroll
            for (int nj = 0; nj < 4; nj++)
#pragma unroll
                for (int q = 0; q < 4; q++) acc[nj][q] = 0.0f;

            uint32_t bhbase = sb + SM_BH + vv * 4096;
#pragma unroll
            for (int kk = 0; kk < 4; kk++) {
                int krow = kk * 16 + krl;
                uint32_t rowb = bhbase + krow * 64;
                uint32_t sw = (uint32_t)((krow >> 1) & 3);
                uint32_t bf0[4], bf1[4];
                LDSM4T(bf0, rowb + (((uint32_t)hi ^ sw) << 4));
                LDSM4T(bf1, rowb + (((uint32_t)(2 + hi) ^ sw) << 4));
                MMA16816(acc[0], af[kk], bf0[0], bf0[1]);
                MMA16816(acc[1], af[kk], bf0[2], bf0[3]);
                MMA16816(acc[2], af[kk], bf1[0], bf1[1]);
                MMA16816(acc[3], af[kk], bf1[2], bf1[3]);
            }

            int vb = v * 128;
            if (p == 0 || p == 2) {
                float w1 = g_s2t[vb + b1], w2 = g_s2t[vb + b2];
#pragma unroll
                for (int nj = 0; nj < 4; nj++) {
                    Tacc[nj * 4 + 0] += w1 * acc[nj][0];
                    Tacc[nj * 4 + 1] += w1 * acc[nj][1];
                    Tacc[nj * 4 + 2] += w2 * acc[nj][2];
                    Tacc[nj * 4 + 3] += w2 * acc[nj][3];
                }
            } else if (p == 3) {
                float w1 = v1a[0] * g_v2t[0][vb + b1] + v1a[1] * g_v2t[1][vb + b1]
                         + v1a[2] * g_v2t[2][vb + b1];
                float w2 = v1b[0] * g_v2t[0][vb + b2] + v1b[1] * g_v2t[1][vb + b2]
                         + v1b[2] * g_v2t[2][vb + b2];
#pragma unroll
                for (int nj = 0; nj < 4; nj++) {
                    Tacc[nj * 4 + 0] += w1 * acc[nj][0];
                    Tacc[nj * 4 + 1] += w1 * acc[nj][1];
                    Tacc[nj * 4 + 2] += w2 * acc[nj][2];
                    Tacc[nj * 4 + 3] += w2 * acc[nj][3];
                }
            } else {
                float wa[3], wb[3];
                if (p == 1) {
#pragma unroll
                    for (int j = 0; j < 3; j++) {
                        wa[j] = g_v2t[j][vb + b1];
                        wb[j] = g_v2t[j][vb + b2];
                    }
                } else {  // p == 4: cross(v1, v2)
                    float y0 = g_v2t[0][vb + b1], y1 = g_v2t[1][vb + b1], y2 = g_v2t[2][vb + b1];
                    wa[0] = v1a[1] * y2 - v1a[2] * y1;
                    wa[1] = v1a[2] * y0 - v1a[0] * y2;
                    wa[2] = v1a[0] * y1 - v1a[1] * y0;
                    float z0 = g_v2t[0][vb + b2], z1 = g_v2t[1][vb + b2], z2 = g_v2t[2][vb + b2];
                    wb[0] = v1b[1] * z2 - v1b[2] * z1;
                    wb[1] = v1b[2] * z0 - v1b[0] * z2;
                    wb[2] = v1b[0] * z1 - v1b[1] * z0;
                }
#pragma unroll
                for (int s = 0; s < 3; s++)
#pragma unroll
                    for (int nj = 0; nj < 4; nj++) {
                        Tacc[s * 16 + nj * 4 + 0] += wa[s] * acc[nj][0];
                        Tacc[s * 16 + nj * 4 + 1] += wa[s] * acc[nj][1];
                        Tacc[s * 16 + nj * 4 + 2] += wb[s] * acc[nj][2];
                        Tacc[s * 16 + nj * 4 + 3] += wb[s] * acc[nj][3];
                    }
            }
        }
    }

    // ---- epilogue: apply u-factor, atomicAdd into g_T ----
    int wb0 = wh * 32 + (lane & 3) * 2;

    auto at_rows = [&](int row1, int row2, int set, float f1, float f2) {
#pragma unroll
        for (int nj = 0; nj < 4; nj++) {
            int w = wb0 + nj * 8;
            atomicAdd(&g_T[row1 * 64 + w],     f1 * Tacc[set * 16 + nj * 4 + 0]);
            atomicAdd(&g_T[row1 * 64 + w + 1], f1 * Tacc[set * 16 + nj * 4 + 1]);
            atomicAdd(&g_T[row2 * 64 + w],     f2 * Tacc[set * 16 + nj * 4 + 2]);
            atomicAdd(&g_T[row2 * 64 + w + 1], f2 * Tacc[set * 16 + nj * 4 + 3]);
        }
    };

    if (p == 0) {
        float s1a = x1[b1 * 256 + u], s1b = x1[b2 * 256 + u];
        at_rows(b1, b2, 0, s1a, s1b);
    } else if (p == 1) {
        float s1a = x1[b1 * 256 + u], s1b = x1[b2 * 256 + u];
#pragma unroll
        for (int j = 0; j < 3; j++)
            at_rows(128 + 3 * b1 + j, 128 + 3 * b2 + j, j, s1a, s1b);
    } else if (p == 2) {
#pragma unroll
        for (int i = 0; i < 3; i++)
            at_rows(512 + 3 * b1 + i, 512 + 3 * b2 + i, 0, v1a[i], v1b[i]);
    } else if (p == 3) {
        at_rows(896 + b1, 896 + b2, 0, 1.0f, 1.0f);
    } else {
#pragma unroll
        for (int k = 0; k < 3; k++)
            at_rows(1024 + 3 * b1 + k, 1024 + 3 * b2 + k, k, 1.0f, 1.0f);
    }
}

// ---------------------------------------------------------------------------
// Kernel 4: combine — assemble output from g_T (360 KB, L2-hot)
// ---------------------------------------------------------------------------
__global__ __launch_bounds__(448) void combine_kernel(float* __restrict__ out)
{
    int b = blockIdx.x;
    int t = threadIdx.x;
    const float C = 0.011048543456039806f;       // 1/(64*sqrt(2))
    const float INV_SQ3 = 0.5773502691896258f;

    if (t < 64) {
        int w = t;
        out[b * 448 + w] = C * (g_T[b * 64 + w] + INV_SQ3 * g_T[(896 + b) * 64 + w]);
    } else if (t < 256) {
        int i = t - 64;
        int w = i / 3, c = i % 3;
        out[b * 448 + 64 + w * 3 + c] =
            C * (g_T[(128 + b * 3 + c) * 64 + w] + g_T[(512 + b * 3 + c) * 64 + w]);
    } else {
        int i = t - 256;
        int w = i / 3, k = i % 3;
        out[b * 448 + 256 + w * 3 + k] = C * g_T[(1024 + b * 3 + k) * 64 + w];
    }
}

// ---------------------------------------------------------------------------
static double host_phi_c()
{
    const double dz = 16.0 / 4000.0;
    const double inv_sqrt2pi = 0.3989422804014327;
    double sum = 0.0, prev = 0.0;
    for (int i = 0; i <= 4000; i++) {
        double z = -8.0 + dz * (double)i;
        float xf = (float)z;
        float x3 = xf * xf * xf;
        float gg = 0.5f * xf * (1.0f + tanhf(0.7978845608028654f * (xf + 0.044715f * x3)));
        double f = (double)gg * (double)gg * exp(-0.5 * z * z) * inv_sqrt2pi;
        if (i > 0) sum += 0.5 * (f + prev) * dz;
        prev = f;
    }
    return sqrt(sum);
}

extern "C" void kernel_launch(void* const* d_in, const int* in_sizes, int n_in,
                              void* d_out, int out_size)
{
    const float* emb = (const float*)d_in[0];
    const float* x1  = (const float*)d_in[1];
    const float* x2  = (const float*)d_in[2];
    const float* W0  = (const float*)d_in[3];
    const float* W1  = (const float*)d_in[4];
    const float* W2  = (const float*)d_in[5];
    const float* P0  = (const float*)d_in[6];
    const float* P1  = (const float*)d_in[7];
    const float* P2  = (const float*)d_in[8];
    const float* P3  = (const float*)d_in[9];
    const float* P4  = (const float*)d_in[10];
    float* out = (float*)d_out;

    float phi_inv = (float)(1.0 / host_phi_c());

    cudaFuncSetAttribute(fused_kernel,
                         cudaFuncAttributeMaxDynamicSharedMemorySize, FUSED_DSMEM);

    mlp_kernel<<<128, 256>>>(emb, W0, W1, W2, phi_inv);
    prepW_kernel<<<64, 128>>>(x2);
    zeroT_kernel<<<88, 1024>>>();
    fused_kernel<<<dim3(64, 2, 10), 256, FUSED_DSMEM>>>(P0, P1, P2, P3, P4, x1);
    combine_kernel<<<128, 448>>>(out);
}

// round 11
// speedup vs baseline: 2.4364x; 1.1994x over previous
#include <cuda_runtime.h>
#include <cuda_fp16.h>
#include <math.h>
#include <stdint.h>

// ---------------------------------------------------------------------------
// TensorProductMultiLayerPerceptron — Round 10: R9 pipeline with the wtab
// WAR race fixed (4-deep weight-table ring; praw 3-deep; bh 2-deep).
//
// For each (p, u, wh, kz) CTA, loop quads of 2 v (16 iterations over 32 v):
//   Bb[b, w] = sum_x hs[b,x] * P_p[x, u, v, w]        (fp16 mma, fp32 acc)
//   T_acc[set][b, w] += weight_p(b, v) * Bb[b, w]     (registers, w from smem)
// Epilogue: apply u-factor, atomicAdd into g_T[1408 x 64]; combine assembles.
// ---------------------------------------------------------------------------

#define NROWS 1408

__device__ __half g_hsh[128 * 64];
__device__ float  g_s2t[64 * 128];        // [v][b] = s2[b,v]
__device__ float  g_v2t[3][64 * 128];     // [j][v][b] = v2[b,v,j]
__device__ float  g_T[NROWS * 64];

// ---------------- helpers ----------------
__device__ __forceinline__ uint32_t smem_u32(const void* p) {
    uint32_t a;
    asm("{ .reg .u64 t; cvta.to.shared.u64 t, %1; cvt.u32.u64 %0, t; }"
        : "=r"(a) : "l"(p));
    return a;
}
__device__ __forceinline__ void cp16(uint32_t s, const void* g) {
    asm volatile("cp.async.cg.shared.global [%0], [%1], 16;\n" :: "r"(s), "l"(g));
}
#define CP_COMMIT() asm volatile("cp.async.commit_group;\n" ::: "memory")
#define CP_WAIT(n)  asm volatile("cp.async.wait_group %0;\n" :: "n"(n) : "memory")

#define LDSM4(r, addr) \
    asm volatile("ldmatrix.sync.aligned.m8n8.x4.shared.b16 {%0,%1,%2,%3}, [%4];" \
        : "=r"((r)[0]), "=r"((r)[1]), "=r"((r)[2]), "=r"((r)[3]) : "r"(addr))
#define LDSM4T(r, addr) \
    asm volatile("ldmatrix.sync.aligned.m8n8.x4.trans.shared.b16 {%0,%1,%2,%3}, [%4];" \
        : "=r"((r)[0]), "=r"((r)[1]), "=r"((r)[2]), "=r"((r)[3]) : "r"(addr))
#define MMA16816(d, a, b0, b1) \
    asm volatile("mma.sync.aligned.m16n8k16.row.col.f32.f16.f16.f32 " \
        "{%0,%1,%2,%3},{%4,%5,%6,%7},{%8,%9},{%0,%1,%2,%3};" \
        : "+f"((d)[0]), "+f"((d)[1]), "+f"((d)[2]), "+f"((d)[3]) \
        : "r"((a)[0]), "r"((a)[1]), "r"((a)[2]), "r"((a)[3]), "r"(b0), "r"(b1))

__device__ __forceinline__ uint32_t pack_h2(float a, float b) {
    __half2 h = __floats2half2_rn(a, b);
    return *reinterpret_cast<uint32_t*>(&h);
}
__device__ __forceinline__ float gelu_tanh(float x) {
    float x3 = x * x * x;
    return 0.5f * x * (1.0f + tanhf(0.7978845608028654f * (x + 0.044715f * x3)));
}

// ---------------------------------------------------------------------------
// Kernel 1: MLP  emb(128x64) -> hs fp16
// ---------------------------------------------------------------------------
__global__ __launch_bounds__(256) void mlp_kernel(
    const float* __restrict__ emb, const float* __restrict__ W0,
    const float* __restrict__ W1, const float* __restrict__ W2, float phi_inv)
{
    __shared__ float sa[256];
    __shared__ float sb[256];
    int b = blockIdx.x;
    int t = threadIdx.x;

    if (t < 64) sa[t] = emb[b * 64 + t];
    __syncthreads();

    float acc = 0.0f;
#pragma unroll 8
    for (int k = 0; k < 64; k++) acc += sa[k] * W0[k * 256 + t];
    sb[t] = gelu_tanh(acc * 0.125f) * phi_inv;
    __syncthreads();

    acc = 0.0f;
#pragma unroll 8
    for (int k = 0; k < 256; k++) acc += sb[k] * W1[k * 256 + t];
    float v2l = gelu_tanh(acc * 0.0625f) * phi_inv;
    __syncthreads();
    sa[t] = v2l;
    __syncthreads();

    if (t < 64) {
        acc = 0.0f;
#pragma unroll 8
        for (int k = 0; k < 256; k++) acc += sa[k] * W2[k * 64 + t];
        g_hsh[b * 64 + t] = __float2half(gelu_tanh(acc * 0.0625f) * phi_inv * 0.125f);
    }
}

// ---------------------------------------------------------------------------
// Kernel 2: weight tables + zero g_T  (grid 88, block 1024)
// ---------------------------------------------------------------------------
__global__ __launch_bounds__(1024) void prep_kernel(const float* __restrict__ x2)
{
    int idx = blockIdx.x * 1024 + threadIdx.x;
    if (idx < NROWS * 64) g_T[idx] = 0.0f;
    if (blockIdx.x < 8) {
        int v = blockIdx.x * 8 + (threadIdx.x >> 7);
        int b = threadIdx.x & 127;
        g_s2t[v * 128 + b] = x2[b * 256 + v];
#pragma unroll
        for (int j = 0; j < 3; j++)
            g_v2t[j][v * 128 + b] = x2[b * 256 + 64 + v * 3 + j];
    }
}

// ---------------------------------------------------------------------------
// Kernel 3: fused GEMM.  grid (64 u, 2 wh, 10 = p*2+kz), 256 threads.
// smem: hs 16K | praw 3 x 16K (2-v quads fp32) | wtab 4 x 3K | bh 2 x 8K.
// Pipeline (1 barrier/iter): issue q(i+3); wait; MMA quad i; convert q(i+1).
// wtab is 4-deep: quad i reads wtab[i&3], quad i+3 writes wtab[(i+3)&3] —
// never the same buffer (the 3-deep ring in R9 aliased them: the race).
// ---------------------------------------------------------------------------
#define SM_HS 0
#define SM_PR 16384
#define SM_WT 65536
#define SM_BH 77824
#define FUSED_DSMEM 94208
#define NQUAD 16

extern __shared__ char dsm[];

__global__ void __launch_bounds__(256, 2) fused_kernel(
    const float* __restrict__ p0, const float* __restrict__ p1,
    const float* __restrict__ p2, const float* __restrict__ p3,
    const float* __restrict__ p4, const float* __restrict__ x1)
{
    uint32_t sb = smem_u32(dsm);

    int t = threadIdx.x;
    int lane = t & 31;
    int warp = t >> 5;           // 0..7 -> m16 tile
    int u  = blockIdx.x;         // 0..63
    int wh = blockIdx.y;         // 0..1
    int p  = blockIdx.z >> 1;    // 0..4
    int kz = blockIdx.z & 1;     // 0..1
    int v0 = kz * 32;

    const float* P = (p == 0) ? p0 : (p == 1) ? p1 : (p == 2) ? p2
                   : (p == 3) ? p3 : p4;
    bool lightW = (p == 0 || p == 2);

    // ---- stage hs (128 x 64 fp16, swizzled) ----
#pragma unroll
    for (int j = 0; j < 4; j++) {
        int idx = t + j * 256;
        int m = idx >> 3, c = idx & 7;
        cp16(sb + SM_HS + m * 128 + ((c ^ (m & 7)) << 4), g_hsh + m * 64 + c * 8);
    }

    // P loader coords: per quad (2 v), thread loads 4 chunks of 16B.
    const float* pbase = P + (size_t)((t >> 3) * 64 + u) * 4096
                       + (size_t)v0 * 64 + wh * 32 + (t & 7) * 4;
    uint32_t pdst = (uint32_t)(SM_PR + (t >> 3) * 128 + (t & 7) * 16);
    const size_t XSTEP = (size_t)32 * 64 * 4096;   // x += 32

    // issue quad q (praw buf q%3, wtab buf q&3), no commit
    auto issue_quad = [&](int q) {
        const float* src = pbase + (size_t)q * 128;
        uint32_t d = sb + pdst + (uint32_t)(q % 3) * 16384;
#pragma unroll
        for (int j = 0; j < 4; j++)
            cp16(d + (j >> 1) * 8192 + (j & 1) * 4096,
                 src + (j & 1) * XSTEP + (size_t)(j >> 1) * 64);
        int v = v0 + q * 2;
        uint32_t wd = sb + SM_WT + (uint32_t)(q & 3) * 3072;
        if (lightW) {
            if (t < 64)
                cp16(wd + (t >> 5) * 1536 + (t & 31) * 16,
                     g_s2t + (size_t)(v + (t >> 5)) * 128 + (t & 31) * 4);
        } else {
            if (t < 192) {
                int vv = t / 96, rem = t - vv * 96, j = rem >> 5, cc = rem & 31;
                cp16(wd + vv * 1536 + j * 512 + cc * 16,
                     g_v2t[j] + (size_t)(v + vv) * 128 + cc * 4);
            }
        }
    };

    // prologue: groups = {hs+q0}, {q1}, {q2}
    issue_quad(0); CP_COMMIT();
    issue_quad(1); CP_COMMIT();
    issue_quad(2); CP_COMMIT();

    CP_WAIT(2);                  // hs + q0 arrived
    __syncthreads();

    // persistent hs A-fragments
    uint32_t af[4][4];
    {
        int row = warp * 16 + (lane & 15);
        int h2 = lane >> 4;
#pragma unroll
        for (int kk = 0; kk < 4; kk++) {
            int c = kk * 2 + h2;
            LDSM4(af[kk], sb + SM_HS + row * 128 + ((c ^ (row & 7)) << 4));
        }
    }

    int b1 = warp * 16 + (lane >> 2);
    int b2 = b1 + 8;
    float v1a[3], v1b[3];
#pragma unroll
    for (int i = 0; i < 3; i++) {
        v1a[i] = x1[b1 * 256 + 64 + u * 3 + i];
        v1b[i] = x1[b2 * 256 + 64 + u * 3 + i];
    }

    float Tacc[48];
#pragma unroll
    for (int i = 0; i < 48; i++) Tacc[i] = 0.0f;

    int hi = lane >> 4;
    int krl = lane & 15;

    // convert coords
    int kq = t >> 2, cq = t & 3;
    uint32_t cvt_src = (uint32_t)(SM_PR + kq * 128 + cq * 32);
    uint32_t cvt_dst = (uint32_t)(SM_BH + kq * 64 + ((cq ^ ((kq >> 1) & 3)) << 4));

    auto convert_quad = [&](int q) {   // praw[q%3] -> bh[q&1]
        const char* srcb = dsm + cvt_src + (q % 3) * 16384;
        char* dstb = dsm + cvt_dst + (q & 1) * 8192;
#pragma unroll
        for (int vv = 0; vv < 2; vv++) {
            const float4* src = (const float4*)(srcb + vv * 8192);
            float4 f0 = src[0], f1 = src[1];
            *(uint4*)(dstb + vv * 4096) =
                make_uint4(pack_h2(f0.x, f0.y), pack_h2(f0.z, f0.w),
                           pack_h2(f1.x, f1.y), pack_h2(f1.z, f1.w));
        }
    };

    // prologue: convert q0 -> bh[0]; ensure q1 arrived; publish
    convert_quad(0);
    CP_WAIT(1);
    __syncthreads();

    // ================= main loop: 16 quads of 2 v =================
#pragma unroll 1
    for (int i = 0; i < NQUAD; i++) {
        if (i + 3 < NQUAD) { issue_quad(i + 3); CP_COMMIT(); CP_WAIT(1); }
        else CP_WAIT(0);

        // ---- MMA quad i (bh[i&1]) + weighted accumulate ----
        const float* wt = (const float*)(dsm + SM_WT + (i & 3) * 3072);
        uint32_t bhq = sb + SM_BH + (i & 1) * 8192;

#pragma unroll
        for (int vv = 0; vv < 2; vv++) {
            float acc[4][4];
#pragma unroll
            for (int nj = 0; nj < 4; nj++)
#pragma unroll
                for (int q = 0; q < 4; q++) acc[nj][q] = 0.0f;

            uint32_t bhbase = bhq + vv * 4096;
#pragma unroll
            for (int kk = 0; kk < 4; kk++) {
                int krow = kk * 16 + krl;
                uint32_t rowb = bhbase + krow * 64;
                uint32_t sw = (uint32_t)((krow >> 1) & 3);
                uint32_t bf0[4], bf1[4];
                LDSM4T(bf0, rowb + (((uint32_t)hi ^ sw) << 4));
                LDSM4T(bf1, rowb + (((uint32_t)(2 + hi) ^ sw) << 4));
                MMA16816(acc[0], af[kk], bf0[0], bf0[1]);
                MMA16816(acc[1], af[kk], bf0[2], bf0[3]);
                MMA16816(acc[2], af[kk], bf1[0], bf1[1]);
                MMA16816(acc[3], af[kk], bf1[2], bf1[3]);
            }

            int wb = vv * 384;
            if (p == 0 || p == 2) {
                float w1 = wt[wb + b1], w2 = wt[wb + b2];
#pragma unroll
                for (int nj = 0; nj < 4; nj++) {
                    Tacc[nj * 4 + 0] += w1 * acc[nj][0];
                    Tacc[nj * 4 + 1] += w1 * acc[nj][1];
                    Tacc[nj * 4 + 2] += w2 * acc[nj][2];
                    Tacc[nj * 4 + 3] += w2 * acc[nj][3];
                }
            } else if (p == 3) {
                float w1 = v1a[0] * wt[wb + b1] + v1a[1] * wt[wb + 128 + b1]
                         + v1a[2] * wt[wb + 256 + b1];
                float w2 = v1b[0] * wt[wb + b2] + v1b[1] * wt[wb + 128 + b2]
                         + v1b[2] * wt[wb + 256 + b2];
#pragma unroll
                for (int nj = 0; nj < 4; nj++) {
                    Tacc[nj * 4 + 0] += w1 * acc[nj][0];
                    Tacc[nj * 4 + 1] += w1 * acc[nj][1];
                    Tacc[nj * 4 + 2] += w2 * acc[nj][2];
                    Tacc[nj * 4 + 3] += w2 * acc[nj][3];
                }
            } else {
                float wa[3], wb3[3];
                if (p == 1) {
#pragma unroll
                    for (int j = 0; j < 3; j++) {
                        wa[j]  = wt[wb + j * 128 + b1];
                        wb3[j] = wt[wb + j * 128 + b2];
                    }
                } else {  // p == 4: cross(v1, v2)
                    float y0 = wt[wb + b1], y1 = wt[wb + 128 + b1], y2 = wt[wb + 256 + b1];
                    wa[0] = v1a[1] * y2 - v1a[2] * y1;
                    wa[1] = v1a[2] * y0 - v1a[0] * y2;
                    wa[2] = v1a[0] * y1 - v1a[1] * y0;
                    float z0 = wt[wb + b2], z1 = wt[wb + 128 + b2], z2 = wt[wb + 256 + b2];
                    wb3[0] = v1b[1] * z2 - v1b[2] * z1;
                    wb3[1] = v1b[2] * z0 - v1b[0] * z2;
                    wb3[2] = v1b[0] * z1 - v1b[1] * z0;
                }
#pragma unroll
                for (int s = 0; s < 3; s++)
#pragma unroll
                    for (int nj = 0; nj < 4; nj++) {
                        Tacc[s * 16 + nj * 4 + 0] += wa[s]  * acc[nj][0];
                        Tacc[s * 16 + nj * 4 + 1] += wa[s]  * acc[nj][1];
                        Tacc[s * 16 + nj * 4 + 2] += wb3[s] * acc[nj][2];
                        Tacc[s * 16 + nj * 4 + 3] += wb3[s] * acc[nj][3];
                    }
            }
        }

        // ---- convert quad i+1 -> bh[(i+1)&1] (overlaps MMA drain) ----
        if (i + 1 < NQUAD) convert_quad(i + 1);
        __syncthreads();
    }

    // ---- epilogue: apply u-factor, atomicAdd into g_T ----
    int wb0 = wh * 32 + (lane & 3) * 2;

    auto at_rows = [&](int row1, int row2, int set, float f1, float f2) {
#pragma unroll
        for (int nj = 0; nj < 4; nj++) {
            int w = wb0 + nj * 8;
            atomicAdd(&g_T[row1 * 64 + w],     f1 * Tacc[set * 16 + nj * 4 + 0]);
            atomicAdd(&g_T[row1 * 64 + w + 1], f1 * Tacc[set * 16 + nj * 4 + 1]);
            atomicAdd(&g_T[row2 * 64 + w],     f2 * Tacc[set * 16 + nj * 4 + 2]);
            atomicAdd(&g_T[row2 * 64 + w + 1], f2 * Tacc[set * 16 + nj * 4 + 3]);
        }
    };

    if (p == 0) {
        float s1a = x1[b1 * 256 + u], s1b = x1[b2 * 256 + u];
        at_rows(b1, b2, 0, s1a, s1b);
    } else if (p == 1) {
        float s1a = x1[b1 * 256 + u], s1b = x1[b2 * 256 + u];
#pragma unroll
        for (int j = 0; j < 3; j++)
            at_rows(128 + 3 * b1 + j, 128 + 3 * b2 + j, j, s1a, s1b);
    } else if (p == 2) {
#pragma unroll
        for (int i = 0; i < 3; i++)
            at_rows(512 + 3 * b1 + i, 512 + 3 * b2 + i, 0, v1a[i], v1b[i]);
    } else if (p == 3) {
        at_rows(896 + b1, 896 + b2, 0, 1.0f, 1.0f);
    } else {
#pragma unroll
        for (int k = 0; k < 3; k++)
            at_rows(1024 + 3 * b1 + k, 1024 + 3 * b2 + k, k, 1.0f, 1.0f);
    }
}

// ---------------------------------------------------------------------------
// Kernel 4: combine — assemble output from g_T (360 KB, L2-hot)
// ---------------------------------------------------------------------------
__global__ __launch_bounds__(448) void combine_kernel(float* __restrict__ out)
{
    int b = blockIdx.x;
    int t = threadIdx.x;
    const float C = 0.011048543456039806f;       // 1/(64*sqrt(2))
    const float INV_SQ3 = 0.5773502691896258f;

    if (t < 64) {
        int w = t;
        out[b * 448 + w] = C * (g_T[b * 64 + w] + INV_SQ3 * g_T[(896 + b) * 64 + w]);
    } else if (t < 256) {
        int i = t - 64;
        int w = i / 3, c = i % 3;
        out[b * 448 + 64 + w * 3 + c] =
            C * (g_T[(128 + b * 3 + c) * 64 + w] + g_T[(512 + b * 3 + c) * 64 + w]);
    } else {
        int i = t - 256;
        int w = i / 3, k = i % 3;
        out[b * 448 + 256 + w * 3 + k] = C * g_T[(1024 + b * 3 + k) * 64 + w];
    }
}

// ---------------------------------------------------------------------------
static double host_phi_c()
{
    const double dz = 16.0 / 4000.0;
    const double inv_sqrt2pi = 0.3989422804014327;
    double sum = 0.0, prev = 0.0;
    for (int i = 0; i <= 4000; i++) {
        double z = -8.0 + dz * (double)i;
        float xf = (float)z;
        float x3 = xf * xf * xf;
        float gg = 0.5f * xf * (1.0f + tanhf(0.7978845608028654f * (xf + 0.044715f * x3)));
        double f = (double)gg * (double)gg * exp(-0.5 * z * z) * inv_sqrt2pi;
        if (i > 0) sum += 0.5 * (f + prev) * dz;
        prev = f;
    }
    return sqrt(sum);
}

extern "C" void kernel_launch(void* const* d_in, const int* in_sizes, int n_in,
                              void* d_out, int out_size)
{
    const float* emb = (const float*)d_in[0];
    const float* x1  = (const float*)d_in[1];
    const float* x2  = (const float*)d_in[2];
    const float* W0  = (const float*)d_in[3];
    const float* W1  = (const float*)d_in[4];
    const float* W2  = (const float*)d_in[5];
    const float* P0  = (const float*)d_in[6];
    const float* P1  = (const float*)d_in[7];
    const float* P2  = (const float*)d_in[8];
    const float* P3  = (const float*)d_in[9];
    const float* P4  = (const float*)d_in[10];
    float* out = (float*)d_out;

    float phi_inv = (float)(1.0 / host_phi_c());

    cudaFuncSetAttribute(fused_kernel,
                         cudaFuncAttributeMaxDynamicSharedMemorySize, FUSED_DSMEM);

    mlp_kernel<<<128, 256>>>(emb, W0, W1, W2, phi_inv);
    prep_kernel<<<88, 1024>>>(x2);
    fused_kernel<<<dim3(64, 2, 10), 256, FUSED_DSMEM>>>(P0, P1, P2, P3, P4, x1);
    combine_kernel<<<128, 448>>>(out);
}